// round 4
// baseline (speedup 1.0000x reference)
#include <cuda_runtime.h>
#include <cstdint>

// Voxelization: c = floor((p.xyz - mn) * inv_vs); invalid -> -1. Output f32 (3,N).
// mn = (0,-40,-3), inv_vs = (20,20,10) (exact f32 reciprocals), grid = (1408,1600,40).
// rel_err was 0.0 with the multiply transform — it is exact on this data.

__device__ __forceinline__ void voxel_one(float px, float py, float pz,
                                          float& cx, float& cy, float& cz) {
    float fx = floorf(px * 20.0f);
    float fy = floorf((py + 40.0f) * 20.0f);
    float fz = floorf((pz + 3.0f) * 10.0f);
    int ix = (int)fx;
    int iy = (int)fy;
    int iz = (int)fz;
    bool valid = (ix >= 0) & (ix < 1408) &
                 (iy >= 0) & (iy < 1600) &
                 (iz >= 0) & (iz < 40);
    cx = valid ? (float)ix : -1.0f;
    cy = valid ? (float)iy : -1.0f;
    cz = valid ? (float)iz : -1.0f;
}

// Each thread processes 8 points: 8 front-batched float4 loads (MLP=8),
// then 6 float4 stores (2 per output row).
__global__ void voxelize_vec8(const float4* __restrict__ pts,
                              float* __restrict__ out,
                              int n8, int n) {
    int i = blockIdx.x * blockDim.x + threadIdx.x;
    if (i >= n8) return;

    float4 p[8];
#pragma unroll
    for (int k = 0; k < 8; k++) p[k] = pts[i * 8 + k];

    float4 ox0, oy0, oz0, ox1, oy1, oz1;
    voxel_one(p[0].x, p[0].y, p[0].z, ox0.x, oy0.x, oz0.x);
    voxel_one(p[1].x, p[1].y, p[1].z, ox0.y, oy0.y, oz0.y);
    voxel_one(p[2].x, p[2].y, p[2].z, ox0.z, oy0.z, oz0.z);
    voxel_one(p[3].x, p[3].y, p[3].z, ox0.w, oy0.w, oz0.w);
    voxel_one(p[4].x, p[4].y, p[4].z, ox1.x, oy1.x, oz1.x);
    voxel_one(p[5].x, p[5].y, p[5].z, ox1.y, oy1.y, oz1.y);
    voxel_one(p[6].x, p[6].y, p[6].z, ox1.z, oy1.z, oz1.z);
    voxel_one(p[7].x, p[7].y, p[7].z, ox1.w, oy1.w, oz1.w);

    // Output row r starts at out + r*n; this thread owns points [8i, 8i+8).
    reinterpret_cast<float4*>(out)[2 * i]             = ox0;
    reinterpret_cast<float4*>(out)[2 * i + 1]         = ox1;
    reinterpret_cast<float4*>(out + n)[2 * i]         = oy0;
    reinterpret_cast<float4*>(out + n)[2 * i + 1]     = oy1;
    reinterpret_cast<float4*>(out + 2 * n)[2 * i]     = oz0;
    reinterpret_cast<float4*>(out + 2 * n)[2 * i + 1] = oz1;
}

// Scalar tail for n not divisible by 8.
__global__ void voxelize_tail(const float4* __restrict__ pts,
                              float* __restrict__ out,
                              int start, int n) {
    int i = start + blockIdx.x * blockDim.x + threadIdx.x;
    if (i >= n) return;
    float4 p = pts[i];
    float cx, cy, cz;
    voxel_one(p.x, p.y, p.z, cx, cy, cz);
    out[i]         = cx;
    out[n + i]     = cy;
    out[2 * n + i] = cz;
}

extern "C" void kernel_launch(void* const* d_in, const int* in_sizes, int n_in,
                              void* d_out, int out_size) {
    const float4* pts = (const float4*)d_in[0];
    float* out = (float*)d_out;
    int n = in_sizes[0] / 4;   // points: (N, 4) float32
    int n8 = n / 8;

    if (n8 > 0) {
        const int T = 256;
        int blocks = (n8 + T - 1) / T;
        voxelize_vec8<<<blocks, T>>>(pts, out, n8, n);
    }
    int tail = n - n8 * 8;
    if (tail > 0) {
        const int T = 128;
        int blocks = (tail + T - 1) / T;
        voxelize_tail<<<blocks, T>>>(pts, out, n8 * 8, n);
    }
}

// round 5
// speedup vs baseline: 1.2673x; 1.2673x over previous
#include <cuda_runtime.h>
#include <cstdint>

// Voxelization: c = floor((p.xyz - mn) * inv_vs); invalid -> -1. Output f32 (3,N).
// mn = (0,-40,-3), inv_vs = (20,20,10) (exact f32 reciprocals, rel_err==0 measured),
// grid = (1408,1600,40).
//
// Layout: block of 256 threads owns 1024 consecutive points. Thread t handles
// points {blk + t, blk + 256 + t, blk + 512 + t, blk + 768 + t}:
//   - 4 front-batched LDG.128, each one a fully contiguous 4KB warp transaction
//   - 12 STG.32, each fully coalesced within the warp
// Register pressure stays low (no local-memory demotion).

__device__ __forceinline__ void voxel_one(float px, float py, float pz,
                                          float& cx, float& cy, float& cz) {
    float fx = floorf(px * 20.0f);
    float fy = floorf((py + 40.0f) * 20.0f);
    float fz = floorf((pz + 3.0f) * 10.0f);
    int ix = (int)fx;
    int iy = (int)fy;
    int iz = (int)fz;
    bool valid = (ix >= 0) & (ix < 1408) &
                 (iy >= 0) & (iy < 1600) &
                 (iz >= 0) & (iz < 40);
    cx = valid ? (float)ix : -1.0f;
    cy = valid ? (float)iy : -1.0f;
    cz = valid ? (float)iz : -1.0f;
}

__global__ void voxelize_coal(const float4* __restrict__ pts,
                              float* __restrict__ out,
                              int nblk4, int n) {
    // Each block handles 4*blockDim points; full blocks only (no bounds checks
    // in the hot path). nblk4 = number of full 1024-point blocks.
    int blk = blockIdx.x * (blockDim.x * 4);
    int t = threadIdx.x;

    int i0 = blk + t;
    int i1 = i0 + 256;
    int i2 = i0 + 512;
    int i3 = i0 + 768;

    float4 p0 = pts[i0];
    float4 p1 = pts[i1];
    float4 p2 = pts[i2];
    float4 p3 = pts[i3];

    float x0, y0, z0, x1, y1, z1, x2, y2, z2, x3, y3, z3;
    voxel_one(p0.x, p0.y, p0.z, x0, y0, z0);
    voxel_one(p1.x, p1.y, p1.z, x1, y1, z1);
    voxel_one(p2.x, p2.y, p2.z, x2, y2, z2);
    voxel_one(p3.x, p3.y, p3.z, x3, y3, z3);

    float* ox = out;
    float* oy = out + n;
    float* oz = out + 2 * n;

    ox[i0] = x0; ox[i1] = x1; ox[i2] = x2; ox[i3] = x3;
    oy[i0] = y0; oy[i1] = y1; oy[i2] = y2; oy[i3] = y3;
    oz[i0] = z0; oz[i1] = z1; oz[i2] = z2; oz[i3] = z3;
}

// Scalar tail for the remainder.
__global__ void voxelize_tail(const float4* __restrict__ pts,
                              float* __restrict__ out,
                              int start, int n) {
    int i = start + blockIdx.x * blockDim.x + threadIdx.x;
    if (i >= n) return;
    float4 p = pts[i];
    float cx, cy, cz;
    voxel_one(p.x, p.y, p.z, cx, cy, cz);
    out[i]         = cx;
    out[n + i]     = cy;
    out[2 * n + i] = cz;
}

extern "C" void kernel_launch(void* const* d_in, const int* in_sizes, int n_in,
                              void* d_out, int out_size) {
    const float4* pts = (const float4*)d_in[0];
    float* out = (float*)d_out;
    int n = in_sizes[0] / 4;   // points: (N, 4) float32

    const int T = 256;
    const int PER_BLOCK = T * 4;            // 1024 points per block
    int full_blocks = n / PER_BLOCK;

    if (full_blocks > 0) {
        voxelize_coal<<<full_blocks, T>>>(pts, out, full_blocks, n);
    }
    int done = full_blocks * PER_BLOCK;
    int tail = n - done;
    if (tail > 0) {
        int blocks = (tail + 127) / 128;
        voxelize_tail<<<blocks, 128>>>(pts, out, done, n);
    }
}

// round 6
// speedup vs baseline: 1.3368x; 1.0548x over previous
#include <cuda_runtime.h>
#include <cstdint>

// Voxelization: c = floor((p.xyz - mn) * inv_vs); invalid -> -1. Output f32 (3,N).
// mn = (0,-40,-3), inv_vs = (20,20,10) (exact f32 reciprocals, rel_err==0 measured),
// grid = (1408,1600,40).
//
// Single kernel. Block of 256 threads owns 1024 consecutive points; thread t
// handles {base+t, base+256+t, base+512+t, base+768+t}:
//   - up to 4 front-batched LDG.128, each a fully contiguous 4KB warp transaction
//   - up to 12 fully-coalesced STG.32
// The final partial block is handled with per-index predicates (no tail kernel).

__device__ __forceinline__ void voxel_one(float px, float py, float pz,
                                          float& cx, float& cy, float& cz) {
    float fx = floorf(px * 20.0f);
    float fy = floorf((py + 40.0f) * 20.0f);
    float fz = floorf((pz + 3.0f) * 10.0f);
    int ix = (int)fx;
    int iy = (int)fy;
    int iz = (int)fz;
    bool valid = (ix >= 0) & (ix < 1408) &
                 (iy >= 0) & (iy < 1600) &
                 (iz >= 0) & (iz < 40);
    cx = valid ? (float)ix : -1.0f;
    cy = valid ? (float)iy : -1.0f;
    cz = valid ? (float)iz : -1.0f;
}

__global__ void voxelize_coal(const float4* __restrict__ pts,
                              float* __restrict__ out,
                              int n) {
    int base = blockIdx.x * (blockDim.x * 4);
    int t = threadIdx.x;

    int i0 = base + t;
    int i1 = i0 + 256;
    int i2 = i0 + 512;
    int i3 = i0 + 768;

    bool v0 = i0 < n, v1 = i1 < n, v2 = i2 < n, v3 = i3 < n;

    float4 p0, p1, p2, p3;
    if (v0) p0 = pts[i0];
    if (v1) p1 = pts[i1];
    if (v2) p2 = pts[i2];
    if (v3) p3 = pts[i3];

    float x0, y0, z0, x1, y1, z1, x2, y2, z2, x3, y3, z3;
    voxel_one(p0.x, p0.y, p0.z, x0, y0, z0);
    voxel_one(p1.x, p1.y, p1.z, x1, y1, z1);
    voxel_one(p2.x, p2.y, p2.z, x2, y2, z2);
    voxel_one(p3.x, p3.y, p3.z, x3, y3, z3);

    float* ox = out;
    float* oy = out + n;
    float* oz = out + 2 * n;

    if (v0) { ox[i0] = x0; oy[i0] = y0; oz[i0] = z0; }
    if (v1) { ox[i1] = x1; oy[i1] = y1; oz[i1] = z1; }
    if (v2) { ox[i2] = x2; oy[i2] = y2; oz[i2] = z2; }
    if (v3) { ox[i3] = x3; oy[i3] = y3; oz[i3] = z3; }
}

extern "C" void kernel_launch(void* const* d_in, const int* in_sizes, int n_in,
                              void* d_out, int out_size) {
    const float4* pts = (const float4*)d_in[0];
    float* out = (float*)d_out;
    int n = in_sizes[0] / 4;   // points: (N, 4) float32

    const int T = 256;
    const int PER_BLOCK = T * 4;                    // 1024 points per block
    int blocks = (n + PER_BLOCK - 1) / PER_BLOCK;   // covers tail via predicates

    if (blocks > 0) {
        voxelize_coal<<<blocks, T>>>(pts, out, n);
    }
}